// round 7
// baseline (speedup 1.0000x reference)
#include <cuda_runtime.h>

#define DD 4096
#define LL 6
#define BLOCK 1024
// 1024 threads * float4 = 4096 = D; each thread owns 4 columns of every row.

__global__ __launch_bounds__(BLOCK, 1)
void crossnet_dcn_kernel(const float* __restrict__ x0g,
                         const float* __restrict__ wg,
                         const float* __restrict__ bg,
                         float* __restrict__ outg,
                         int B)
{
    __shared__ float s_part[2][32][7];   // [buf][warp][value], 7 coprime 32 -> conflict-free
    __shared__ float s_c[2];             // [buf] -> c scalar
    __shared__ float s_e[LL];            // e_l scalars (constant after preamble)

    const int tid  = threadIdx.x;
    const int lane = tid & 31;
    const int wid  = tid >> 5;

    const float4* w4 = reinterpret_cast<const float4*>(wg);
    const float4* b4 = reinterpret_cast<const float4*>(bg);
    const float4* x4 = reinterpret_cast<const float4*>(x0g);
    float4*       o4 = reinterpret_cast<float4*>(outg);

    // ---- w for this thread's 4 columns, all layers (24 regs) ----
    float4 wr[LL];
#pragma unroll
    for (int l = 0; l < LL; l++) wr[l] = w4[l * (DD / 4) + tid];

    // ---- preamble: d_L (float4, regs) and e_l = d_l . w_l -> s_e ----
    float4 dl = make_float4(0.f, 0.f, 0.f, 0.f);
    {
        float ep[LL];
#pragma unroll
        for (int l = 0; l < LL; l++) {
            ep[l] = dl.x * wr[l].x + dl.y * wr[l].y + dl.z * wr[l].z + dl.w * wr[l].w;
            float4 bv = b4[l * (DD / 4) + tid];
            dl.x += bv.x; dl.y += bv.y; dl.z += bv.z; dl.w += bv.w;
        }
#pragma unroll
        for (int o = 16; o > 0; o >>= 1)
#pragma unroll
            for (int l = 0; l < LL; l++) ep[l] += __shfl_xor_sync(0xffffffffu, ep[l], o);
        if (lane == 0)
#pragma unroll
            for (int l = 0; l < LL; l++) s_part[0][wid][l] = ep[l];
    }
    __syncthreads();
    if (wid == 0) {
#pragma unroll
        for (int l = 0; l < LL; l++) {
            float t = s_part[0][lane][l];
#pragma unroll
            for (int o = 16; o > 0; o >>= 1) t += __shfl_xor_sync(0xffffffffu, t, o);
            if (lane == 0) s_e[l] = t;
        }
    }
    __syncthreads();

    // ---- main loop: ONE row per iteration, ONE barrier per iteration.
    // Stage-2 (warp 0, row i) overlaps epilogue (all warps, row i-1) + prefetch.
    const int stride = gridDim.x;

    int row = blockIdx.x;
    float4 pf = make_float4(0.f, 0.f, 0.f, 0.f);
    if (row < B) pf = __ldcs(&x4[(size_t)row * (DD / 4) + tid]);

    float4 x_prev = pf;
    int    prev_row = 0;
    bool   have_prev = false;
    int    buf = 0;

    for (; row < B; row += stride) {
        const float4 x = pf;

        // prefetch next row (consumed next iteration)
        int nr = row + stride;
        if (nr < B) pf = __ldcs(&x4[(size_t)nr * (DD / 4) + tid]);

        // per-thread partial dots for this row, all 6 layers
        float v[LL];
#pragma unroll
        for (int l = 0; l < LL; l++) {
            float a = x.x * wr[l].x;
            a = fmaf(x.y, wr[l].y, a);
            a = fmaf(x.z, wr[l].z, a);
            a = fmaf(x.w, wr[l].w, a);
            v[l] = a;
        }

        // 6-value transposed warp reduce (rounds 16,8,4 then xor2, xor1).
        // Value l lands replicated on lanes {4l..4l+3}.
        {
            bool hi = (lane & 16) != 0;
#pragma unroll
            for (int j = 0; j < 4; j++) {
                float th   = (j + 4 < LL) ? v[j + 4] : 0.f;
                float send = hi ? v[j] : th;
                float keep = hi ? th : v[j];
                v[j] = keep + __shfl_xor_sync(0xffffffffu, send, 16);
            }
        }
        {
            bool hi = (lane & 8) != 0;
#pragma unroll
            for (int j = 0; j < 2; j++) {
                float send = hi ? v[j] : v[j + 2];
                float keep = hi ? v[j + 2] : v[j];
                v[j] = keep + __shfl_xor_sync(0xffffffffu, send, 8);
            }
        }
        {
            bool hi = (lane & 4) != 0;
            float send = hi ? v[0] : v[1];
            float keep = hi ? v[1] : v[0];
            v[0] = keep + __shfl_xor_sync(0xffffffffu, send, 4);
        }
        v[0] += __shfl_xor_sync(0xffffffffu, v[0], 2);
        v[0] += __shfl_xor_sync(0xffffffffu, v[0], 1);

        // lane 4l (l<6) stores warp-partial l: one predicated STS
        if ((lane & 3) == 0 && lane < 24)
            s_part[buf][wid][lane >> 2] = v[0];

        __syncthreads();   // the ONLY barrier per iteration

        // ---- warp 0: stage-2 for row i (writes s_c[buf]) ----
        if (wid == 0) {
            float t[LL];
#pragma unroll
            for (int j = 0; j < LL; j++) t[j] = s_part[buf][lane][j];
            {
                bool hi = (lane & 16) != 0;
#pragma unroll
                for (int j = 0; j < 4; j++) {
                    float th   = (j + 4 < LL) ? t[j + 4] : 0.f;
                    float send = hi ? t[j] : th;
                    float keep = hi ? th : t[j];
                    t[j] = keep + __shfl_xor_sync(0xffffffffu, send, 16);
                }
            }
            {
                bool hi = (lane & 8) != 0;
#pragma unroll
                for (int j = 0; j < 2; j++) {
                    float send = hi ? t[j] : t[j + 2];
                    float keep = hi ? t[j + 2] : t[j];
                    t[j] = keep + __shfl_xor_sync(0xffffffffu, send, 8);
                }
            }
            {
                bool hi = (lane & 4) != 0;
                float send = hi ? t[0] : t[1];
                float keep = hi ? t[1] : t[0];
                t[0] = keep + __shfl_xor_sync(0xffffffffu, send, 4);
            }
            t[0] += __shfl_xor_sync(0xffffffffu, t[0], 2);
            t[0] += __shfl_xor_sync(0xffffffffu, t[0], 1);

            // gather u_l (6 independent shfls, pipelined) then scalar recurrence
            float u[LL];
#pragma unroll
            for (int l = 0; l < LL; l++)
                u[l] = __shfl_sync(0xffffffffu, t[0], 4 * l);
            float c = 1.f;
#pragma unroll
            for (int l = 0; l < LL; l++)
                c = fmaf(c, u[l], c + s_e[l]);   // c = c*(1+u) + e
            if (lane == 0) s_c[buf] = c;
        }

        // ---- all warps: epilogue for row i-1 (reads s_c[buf^1], x_prev in regs) ----
        if (have_prev) {
            const float c = s_c[buf ^ 1];
            float4 o;
            o.x = fmaf(x_prev.x, c, dl.x);
            o.y = fmaf(x_prev.y, c, dl.y);
            o.z = fmaf(x_prev.z, c, dl.z);
            o.w = fmaf(x_prev.w, c, dl.w);
            __stcs(&o4[(size_t)prev_row * (DD / 4) + tid], o);
        }

        x_prev   = x;
        prev_row = row;
        have_prev = true;
        buf ^= 1;
    }

    // ---- drain: epilogue for the last processed row ----
    if (have_prev) {
        __syncthreads();   // make warp0's s_c[buf^1] visible
        const float c = s_c[buf ^ 1];
        float4 o;
        o.x = fmaf(x_prev.x, c, dl.x);
        o.y = fmaf(x_prev.y, c, dl.y);
        o.z = fmaf(x_prev.z, c, dl.z);
        o.w = fmaf(x_prev.w, c, dl.w);
        __stcs(&o4[(size_t)prev_row * (DD / 4) + tid], o);
    }
}

extern "C" void kernel_launch(void* const* d_in, const int* in_sizes, int n_in,
                              void* d_out, int out_size)
{
    const float* x0 = (const float*)d_in[0];   // inputs [B, D] f32
    const float* w  = (const float*)d_in[1];   // w [L, D, 1]  f32
    const float* b  = (const float*)d_in[2];   // b [L, D]     f32
    float* out      = (float*)d_out;           // [B, D]       f32

    const int B = in_sizes[0] / DD;

    static int sm_count = 0;
    if (sm_count == 0) {
        cudaDeviceGetAttribute(&sm_count, cudaDevAttrMultiProcessorCount, 0);
        if (sm_count <= 0) sm_count = 148;
    }

    crossnet_dcn_kernel<<<sm_count, BLOCK>>>(x0, w, b, out, B);
}

// round 8
// speedup vs baseline: 1.1169x; 1.1169x over previous
#include <cuda_runtime.h>
#include <cstdint>

#define DD 4096
#define LL 6
#define BLOCK 1024
#define NST 3            // cp.async pipeline stages (4 rows each)

__device__ __forceinline__ void cp_async16(float* dst, const float* src) {
    uint32_t d = (uint32_t)__cvta_generic_to_shared(dst);
    asm volatile("cp.async.cg.shared.global [%0], [%1], 16;" :: "r"(d), "l"(src));
}
__device__ __forceinline__ void cp_commit() { asm volatile("cp.async.commit_group;"); }
__device__ __forceinline__ void cp_wait1()  { asm volatile("cp.async.wait_group 1;" ::: "memory"); }

__global__ __launch_bounds__(BLOCK, 1)
void crossnet_dcn_kernel(const float* __restrict__ x0g,
                         const float* __restrict__ wg,
                         const float* __restrict__ bg,
                         float* __restrict__ outg,
                         int B)
{
    extern __shared__ float xs[];        // NST * 4 * DD floats (x0 staging)
    __shared__ float s_part[32][25];     // 24 reduced values per warp, pad 25
    __shared__ float s_c[4];             // c scalar per row
    __shared__ float s_e[LL];            // e_l scalars

    const int tid  = threadIdx.x;
    const int lane = tid & 31;
    const int wid  = tid >> 5;

    const float4* w4 = reinterpret_cast<const float4*>(wg);
    const float4* b4 = reinterpret_cast<const float4*>(bg);
    float4*       o4 = reinterpret_cast<float4*>(outg);

    // ---- w for this thread's 4 columns, all layers (24 regs) ----
    float4 wr[LL];
#pragma unroll
    for (int l = 0; l < LL; l++) wr[l] = w4[l * (DD / 4) + tid];

    // ---- preamble: d_L (vector, regs) and e_l = d_l . w_l -> s_e ----
    float4 dl = make_float4(0.f, 0.f, 0.f, 0.f);
    {
        float ep[LL];
#pragma unroll
        for (int l = 0; l < LL; l++) {
            ep[l] = dl.x * wr[l].x + dl.y * wr[l].y + dl.z * wr[l].z + dl.w * wr[l].w;
            float4 bv = b4[l * (DD / 4) + tid];
            dl.x += bv.x; dl.y += bv.y; dl.z += bv.z; dl.w += bv.w;
        }
#pragma unroll
        for (int o = 16; o > 0; o >>= 1)
#pragma unroll
            for (int l = 0; l < LL; l++) ep[l] += __shfl_xor_sync(0xffffffffu, ep[l], o);
        if (lane == 0)
#pragma unroll
            for (int l = 0; l < LL; l++) s_part[wid][l] = ep[l];
    }
    __syncthreads();
    if (wid == 0) {
#pragma unroll
        for (int l = 0; l < LL; l++) {
            float t = s_part[lane][l];
#pragma unroll
            for (int o = 16; o > 0; o >>= 1) t += __shfl_xor_sync(0xffffffffu, t, o);
            if (lane == 0) s_e[l] = t;
        }
    }
    __syncthreads();

    // ---- main loop: 4 rows ("quad") per iteration ----
    const int nquads = B >> 2;
    const int stride = gridDim.x;
    const int bid    = blockIdx.x;
    const int niters = (nquads > bid) ? (nquads - bid + stride - 1) / stride : 0;

    auto issue_stage = [&](int ia, int slot) {
        int q = bid + ia * stride;
        if (q < nquads) {
            const float* src = x0g + (size_t)(4 * q) * DD + tid * 4;
            float*       dst = xs + (slot * 4) * DD + tid * 4;
#pragma unroll
            for (int r = 0; r < 4; r++)
                cp_async16(dst + r * DD, src + (size_t)r * DD);
        }
        cp_commit();   // commit even if empty: uniform wait_group accounting
    };

    issue_stage(0, 0);
    issue_stage(1, 1);

    for (int it = 0; it < niters; it++) {
        cp_wait1();                       // slot it%3 ready (own-thread data)
        const int  slot = it % NST;
        const float* xb = xs + (slot * 4) * DD;
        const int  q  = bid + it * stride;

        // ---- load this quad's x into registers (kept through epilogue) ----
        float4 xr0 = *reinterpret_cast<const float4*>(xb + 0 * DD + tid * 4);
        float4 xr1 = *reinterpret_cast<const float4*>(xb + 1 * DD + tid * 4);
        float4 xr2 = *reinterpret_cast<const float4*>(xb + 2 * DD + tid * 4);
        float4 xr3 = *reinterpret_cast<const float4*>(xb + 3 * DD + tid * 4);

        float v[12];

        // ---- half 0: rows 0,1 ----
#pragma unroll
        for (int l = 0; l < LL; l++) {
            float a = xr0.x * wr[l].x;
            a = fmaf(xr0.y, wr[l].y, a);
            a = fmaf(xr0.z, wr[l].z, a);
            a = fmaf(xr0.w, wr[l].w, a);
            v[l] = a;
            float c = xr1.x * wr[l].x;
            c = fmaf(xr1.y, wr[l].y, c);
            c = fmaf(xr1.z, wr[l].z, c);
            c = fmaf(xr1.w, wr[l].w, c);
            v[LL + l] = c;
        }
        {
            bool hi = (lane & 16) != 0;
#pragma unroll
            for (int j = 0; j < 8; j++) {
                float vh   = (j + 8 < 12) ? v[j + 8] : 0.f;
                float send = hi ? v[j] : vh;
                float keep = hi ? vh : v[j];
                v[j] = keep + __shfl_xor_sync(0xffffffffu, send, 16);
            }
        }
#pragma unroll
        for (int r = 1; r < 4; r++) {
            const int dist = 16 >> r;
            const int nv   = 8 >> r;
            bool hi = (lane & dist) != 0;
#pragma unroll
            for (int j = 0; j < nv; j++) {
                float send = hi ? v[j] : v[j + nv];
                float keep = hi ? v[j + nv] : v[j];
                v[j] = keep + __shfl_xor_sync(0xffffffffu, send, dist);
            }
        }
        v[0] += __shfl_xor_sync(0xffffffffu, v[0], 1);
        if ((lane & 1) == 0 && lane < 24)
            s_part[wid][lane >> 1] = v[0];

        // ---- half 1: rows 2,3 (dots first, then refill, then reduce) ----
#pragma unroll
        for (int l = 0; l < LL; l++) {
            float a = xr2.x * wr[l].x;
            a = fmaf(xr2.y, wr[l].y, a);
            a = fmaf(xr2.z, wr[l].z, a);
            a = fmaf(xr2.w, wr[l].w, a);
            v[l] = a;
            float c = xr3.x * wr[l].x;
            c = fmaf(xr3.y, wr[l].y, c);
            c = fmaf(xr3.z, wr[l].z, c);
            c = fmaf(xr3.w, wr[l].w, c);
            v[LL + l] = c;
        }

        // refill: slot (it+2)%3 — this thread's own slices were last read at
        // iter it-1 (program order), safe to overwrite now; maximizes lookahead
        issue_stage(it + 2, (it + 2) % NST);

        {
            bool hi = (lane & 16) != 0;
#pragma unroll
            for (int j = 0; j < 8; j++) {
                float vh   = (j + 8 < 12) ? v[j + 8] : 0.f;
                float send = hi ? v[j] : vh;
                float keep = hi ? vh : v[j];
                v[j] = keep + __shfl_xor_sync(0xffffffffu, send, 16);
            }
        }
#pragma unroll
        for (int r = 1; r < 4; r++) {
            const int dist = 16 >> r;
            const int nv   = 8 >> r;
            bool hi = (lane & dist) != 0;
#pragma unroll
            for (int j = 0; j < nv; j++) {
                float send = hi ? v[j] : v[j + nv];
                float keep = hi ? v[j + nv] : v[j];
                v[j] = keep + __shfl_xor_sync(0xffffffffu, send, dist);
            }
        }
        v[0] += __shfl_xor_sync(0xffffffffu, v[0], 1);
        if ((lane & 1) == 0 && lane < 24)
            s_part[wid][12 + (lane >> 1)] = v[0];

        __syncthreads();   // barrier A

        // ---- stage-2: warp r reduces row r's 6 values over 32 warps ----
        if (wid < 4) {
            float t[6];
#pragma unroll
            for (int l = 0; l < LL; l++) t[l] = s_part[lane][6 * wid + l];
            {
                bool hi = (lane & 16) != 0;
#pragma unroll
                for (int j = 0; j < 4; j++) {
                    float th   = (j + 4 < 6) ? t[j + 4] : 0.f;
                    float send = hi ? t[j] : th;
                    float keep = hi ? th : t[j];
                    t[j] = keep + __shfl_xor_sync(0xffffffffu, send, 16);
                }
            }
            {
                bool hi = (lane & 8) != 0;
#pragma unroll
                for (int j = 0; j < 2; j++) {
                    float send = hi ? t[j] : t[j + 2];
                    float keep = hi ? t[j + 2] : t[j];
                    t[j] = keep + __shfl_xor_sync(0xffffffffu, send, 8);
                }
            }
            {
                bool hi = (lane & 4) != 0;
                float send = hi ? t[0] : t[1];
                float keep = hi ? t[1] : t[0];
                t[0] = keep + __shfl_xor_sync(0xffffffffu, send, 4);
            }
            t[0] += __shfl_xor_sync(0xffffffffu, t[0], 2);
            t[0] += __shfl_xor_sync(0xffffffffu, t[0], 1);

            float c = 1.f;
#pragma unroll
            for (int l = 0; l < LL; l++) {
                float u = __shfl_sync(0xffffffffu, t[0], 4 * l);
                c = fmaf(c, u, c + s_e[l]);   // c = c*(1+u) + e
            }
            if (lane == 0) s_c[wid] = c;
        }

        __syncthreads();   // barrier B

        // ---- epilogue from registers: out[row] = x0 * c_row + d_L ----
        const float c0 = s_c[0], c1 = s_c[1], c2 = s_c[2], c3 = s_c[3];
        float4 o;
        o.x = fmaf(xr0.x, c0, dl.x); o.y = fmaf(xr0.y, c0, dl.y);
        o.z = fmaf(xr0.z, c0, dl.z); o.w = fmaf(xr0.w, c0, dl.w);
        __stcs(&o4[(size_t)(4 * q + 0) * (DD / 4) + tid], o);
        o.x = fmaf(xr1.x, c1, dl.x); o.y = fmaf(xr1.y, c1, dl.y);
        o.z = fmaf(xr1.z, c1, dl.z); o.w = fmaf(xr1.w, c1, dl.w);
        __stcs(&o4[(size_t)(4 * q + 1) * (DD / 4) + tid], o);
        o.x = fmaf(xr2.x, c2, dl.x); o.y = fmaf(xr2.y, c2, dl.y);
        o.z = fmaf(xr2.z, c2, dl.z); o.w = fmaf(xr2.w, c2, dl.w);
        __stcs(&o4[(size_t)(4 * q + 2) * (DD / 4) + tid], o);
        o.x = fmaf(xr3.x, c3, dl.x); o.y = fmaf(xr3.y, c3, dl.y);
        o.z = fmaf(xr3.z, c3, dl.z); o.w = fmaf(xr3.w, c3, dl.w);
        __stcs(&o4[(size_t)(4 * q + 3) * (DD / 4) + tid], o);
    }
}

extern "C" void kernel_launch(void* const* d_in, const int* in_sizes, int n_in,
                              void* d_out, int out_size)
{
    const float* x0 = (const float*)d_in[0];   // inputs [B, D] f32
    const float* w  = (const float*)d_in[1];   // w [L, D, 1]  f32
    const float* b  = (const float*)d_in[2];   // b [L, D]     f32
    float* out      = (float*)d_out;           // [B, D]       f32

    const int B = in_sizes[0] / DD;
    const int smem_bytes = NST * 4 * DD * (int)sizeof(float);   // 196608

    static int sm_count = 0;
    if (sm_count == 0) {
        cudaDeviceGetAttribute(&sm_count, cudaDevAttrMultiProcessorCount, 0);
        if (sm_count <= 0) sm_count = 148;
        cudaFuncSetAttribute(crossnet_dcn_kernel,
                             cudaFuncAttributeMaxDynamicSharedMemorySize,
                             smem_bytes);
    }

    crossnet_dcn_kernel<<<sm_count, BLOCK, smem_bytes>>>(x0, w, b, out, B);
}

// round 9
// speedup vs baseline: 1.2300x; 1.1013x over previous
#include <cuda_runtime.h>
#include <cstdint>

#define DD 4096
#define LL 6
#define BLOCK 1024
#define NST 3            // cp.async pipeline stages (4 rows each)

__device__ __forceinline__ void cp_async16(float* dst, const float* src) {
    uint32_t d = (uint32_t)__cvta_generic_to_shared(dst);
    asm volatile("cp.async.cg.shared.global [%0], [%1], 16;" :: "r"(d), "l"(src));
}
__device__ __forceinline__ void cp_commit() { asm volatile("cp.async.commit_group;"); }
__device__ __forceinline__ void cp_wait1()  { asm volatile("cp.async.wait_group 1;" ::: "memory"); }

__global__ __launch_bounds__(BLOCK, 1)
void crossnet_dcn_kernel(const float* __restrict__ x0g,
                         const float* __restrict__ wg,
                         const float* __restrict__ bg,
                         float* __restrict__ outg,
                         int B)
{
    extern __shared__ float xs[];        // NST * 4 * DD floats (x0 staging)
    __shared__ float s_part[32][25];     // 24 reduced values per warp, pad 25
    __shared__ float s_c[2][4];          // double-buffered c scalars (4 rows)
    __shared__ float s_e[LL];            // e_l scalars

    const int tid  = threadIdx.x;
    const int lane = tid & 31;
    const int wid  = tid >> 5;

    const float4* w4 = reinterpret_cast<const float4*>(wg);
    const float4* b4 = reinterpret_cast<const float4*>(bg);
    float4*       o4 = reinterpret_cast<float4*>(outg);

    // ---- w for this thread's 4 columns, all layers (24 regs) ----
    float4 wr[LL];
#pragma unroll
    for (int l = 0; l < LL; l++) wr[l] = w4[l * (DD / 4) + tid];

    // ---- preamble: d_L (vector, regs) and e_l = d_l . w_l -> s_e ----
    float4 dl = make_float4(0.f, 0.f, 0.f, 0.f);
    {
        float ep[LL];
#pragma unroll
        for (int l = 0; l < LL; l++) {
            ep[l] = dl.x * wr[l].x + dl.y * wr[l].y + dl.z * wr[l].z + dl.w * wr[l].w;
            float4 bv = b4[l * (DD / 4) + tid];
            dl.x += bv.x; dl.y += bv.y; dl.z += bv.z; dl.w += bv.w;
        }
#pragma unroll
        for (int o = 16; o > 0; o >>= 1)
#pragma unroll
            for (int l = 0; l < LL; l++) ep[l] += __shfl_xor_sync(0xffffffffu, ep[l], o);
        if (lane == 0)
#pragma unroll
            for (int l = 0; l < LL; l++) s_part[wid][l] = ep[l];
    }
    __syncthreads();
    if (wid == 0) {
#pragma unroll
        for (int l = 0; l < LL; l++) {
            float t = s_part[lane][l];
#pragma unroll
            for (int o = 16; o > 0; o >>= 1) t += __shfl_xor_sync(0xffffffffu, t, o);
            if (lane == 0) s_e[l] = t;
        }
    }
    __syncthreads();

    // ---- main loop: 4 rows ("quad") per iteration, ONE barrier per iteration.
    // Stage-2 for quad i (warps 0-3) overlaps epilogue for quad i-1 (all warps).
    const int nquads = B >> 2;
    const int stride = gridDim.x;
    const int bid    = blockIdx.x;
    const int niters = (nquads > bid) ? (nquads - bid + stride - 1) / stride : 0;

    auto issue_stage = [&](int ia, int slot) {
        int q = bid + ia * stride;
        if (q < nquads) {
            const float* src = x0g + (size_t)(4 * q) * DD + tid * 4;
            float*       dst = xs + (slot * 4) * DD + tid * 4;
#pragma unroll
            for (int r = 0; r < 4; r++)
                cp_async16(dst + r * DD, src + (size_t)r * DD);
        }
        cp_commit();   // commit even if empty: uniform wait_group accounting
    };

    issue_stage(0, 0);
    issue_stage(1, 1);

    for (int it = 0; it < niters; it++) {
        cp_wait1();                       // slot it%3 ready (own-thread data)
        const int  slot = it % NST;
        const float* xb = xs + (slot * 4) * DD;
        const int  q  = bid + it * stride;
        const int  cur = it & 1;

        float v[12];

        // ---- half 0: rows 0,1 ----
        {
            const float4 xr0 = *reinterpret_cast<const float4*>(xb + 0 * DD + tid * 4);
            const float4 xr1 = *reinterpret_cast<const float4*>(xb + 1 * DD + tid * 4);
#pragma unroll
            for (int l = 0; l < LL; l++) {
                float a = xr0.x * wr[l].x;
                a = fmaf(xr0.y, wr[l].y, a);
                a = fmaf(xr0.z, wr[l].z, a);
                a = fmaf(xr0.w, wr[l].w, a);
                v[l] = a;
                float c = xr1.x * wr[l].x;
                c = fmaf(xr1.y, wr[l].y, c);
                c = fmaf(xr1.z, wr[l].z, c);
                c = fmaf(xr1.w, wr[l].w, c);
                v[LL + l] = c;
            }
        }
        {
            bool hi = (lane & 16) != 0;
#pragma unroll
            for (int j = 0; j < 8; j++) {
                float vh   = (j + 8 < 12) ? v[j + 8] : 0.f;
                float send = hi ? v[j] : vh;
                float keep = hi ? vh : v[j];
                v[j] = keep + __shfl_xor_sync(0xffffffffu, send, 16);
            }
        }
#pragma unroll
        for (int r = 1; r < 4; r++) {
            const int dist = 16 >> r;
            const int nv   = 8 >> r;
            bool hi = (lane & dist) != 0;
#pragma unroll
            for (int j = 0; j < nv; j++) {
                float send = hi ? v[j] : v[j + nv];
                float keep = hi ? v[j + nv] : v[j];
                v[j] = keep + __shfl_xor_sync(0xffffffffu, send, dist);
            }
        }
        v[0] += __shfl_xor_sync(0xffffffffu, v[0], 1);
        if ((lane & 1) == 0 && lane < 24)
            s_part[wid][lane >> 1] = v[0];

        // ---- half 1: rows 2,3 ----
        {
            const float4 xr2 = *reinterpret_cast<const float4*>(xb + 2 * DD + tid * 4);
            const float4 xr3 = *reinterpret_cast<const float4*>(xb + 3 * DD + tid * 4);
#pragma unroll
            for (int l = 0; l < LL; l++) {
                float a = xr2.x * wr[l].x;
                a = fmaf(xr2.y, wr[l].y, a);
                a = fmaf(xr2.z, wr[l].z, a);
                a = fmaf(xr2.w, wr[l].w, a);
                v[l] = a;
                float c = xr3.x * wr[l].x;
                c = fmaf(xr3.y, wr[l].y, c);
                c = fmaf(xr3.z, wr[l].z, c);
                c = fmaf(xr3.w, wr[l].w, c);
                v[LL + l] = c;
            }
        }
        {
            bool hi = (lane & 16) != 0;
#pragma unroll
            for (int j = 0; j < 8; j++) {
                float vh   = (j + 8 < 12) ? v[j + 8] : 0.f;
                float send = hi ? v[j] : vh;
                float keep = hi ? vh : v[j];
                v[j] = keep + __shfl_xor_sync(0xffffffffu, send, 16);
            }
        }
#pragma unroll
        for (int r = 1; r < 4; r++) {
            const int dist = 16 >> r;
            const int nv   = 8 >> r;
            bool hi = (lane & dist) != 0;
#pragma unroll
            for (int j = 0; j < nv; j++) {
                float send = hi ? v[j] : v[j + nv];
                float keep = hi ? v[j + nv] : v[j];
                v[j] = keep + __shfl_xor_sync(0xffffffffu, send, dist);
            }
        }
        v[0] += __shfl_xor_sync(0xffffffffu, v[0], 1);
        if ((lane & 1) == 0 && lane < 24)
            s_part[wid][12 + (lane >> 1)] = v[0];

        __syncthreads();   // the ONLY barrier per iteration

        // ---- warps 0-3: stage-2 for quad i (writes s_c[cur]) ----
        if (wid < 4) {
            float t[6];
#pragma unroll
            for (int l = 0; l < LL; l++) t[l] = s_part[lane][6 * wid + l];
            {
                bool hi = (lane & 16) != 0;
#pragma unroll
                for (int j = 0; j < 4; j++) {
                    float th   = (j + 4 < 6) ? t[j + 4] : 0.f;
                    float send = hi ? t[j] : th;
                    float keep = hi ? th : t[j];
                    t[j] = keep + __shfl_xor_sync(0xffffffffu, send, 16);
                }
            }
            {
                bool hi = (lane & 8) != 0;
#pragma unroll
                for (int j = 0; j < 2; j++) {
                    float send = hi ? t[j] : t[j + 2];
                    float keep = hi ? t[j + 2] : t[j];
                    t[j] = keep + __shfl_xor_sync(0xffffffffu, send, 8);
                }
            }
            {
                bool hi = (lane & 4) != 0;
                float send = hi ? t[0] : t[1];
                float keep = hi ? t[1] : t[0];
                t[0] = keep + __shfl_xor_sync(0xffffffffu, send, 4);
            }
            t[0] += __shfl_xor_sync(0xffffffffu, t[0], 2);
            t[0] += __shfl_xor_sync(0xffffffffu, t[0], 1);

            float c = 1.f;
#pragma unroll
            for (int l = 0; l < LL; l++) {
                float u = __shfl_sync(0xffffffffu, t[0], 4 * l);
                c = fmaf(c, u, c + s_e[l]);   // c = c*(1+u) + e
            }
            if (lane == 0) s_c[cur][wid] = c;
        }

        // ---- all warps: epilogue for quad i-1 (x re-read from its slot) ----
        if (it > 0) {
            const float* pb = xs + (((it - 1) % NST) * 4) * DD;
            const int    qp = q - stride;
            const float  c0 = s_c[cur ^ 1][0], c1 = s_c[cur ^ 1][1];
            const float  c2 = s_c[cur ^ 1][2], c3 = s_c[cur ^ 1][3];
            float4 xp, o;
            xp = *reinterpret_cast<const float4*>(pb + 0 * DD + tid * 4);
            o.x = fmaf(xp.x, c0, dl.x); o.y = fmaf(xp.y, c0, dl.y);
            o.z = fmaf(xp.z, c0, dl.z); o.w = fmaf(xp.w, c0, dl.w);
            __stcs(&o4[(size_t)(4 * qp + 0) * (DD / 4) + tid], o);
            xp = *reinterpret_cast<const float4*>(pb + 1 * DD + tid * 4);
            o.x = fmaf(xp.x, c1, dl.x); o.y = fmaf(xp.y, c1, dl.y);
            o.z = fmaf(xp.z, c1, dl.z); o.w = fmaf(xp.w, c1, dl.w);
            __stcs(&o4[(size_t)(4 * qp + 1) * (DD / 4) + tid], o);
            xp = *reinterpret_cast<const float4*>(pb + 2 * DD + tid * 4);
            o.x = fmaf(xp.x, c2, dl.x); o.y = fmaf(xp.y, c2, dl.y);
            o.z = fmaf(xp.z, c2, dl.z); o.w = fmaf(xp.w, c2, dl.w);
            __stcs(&o4[(size_t)(4 * qp + 2) * (DD / 4) + tid], o);
            xp = *reinterpret_cast<const float4*>(pb + 3 * DD + tid * 4);
            o.x = fmaf(xp.x, c3, dl.x); o.y = fmaf(xp.y, c3, dl.y);
            o.z = fmaf(xp.z, c3, dl.z); o.w = fmaf(xp.w, c3, dl.w);
            __stcs(&o4[(size_t)(4 * qp + 3) * (DD / 4) + tid], o);
        }

        // refill the slot the epilogue just finished reading:
        // (it+2)%3 == (it-1)%3, so this must come AFTER the epilogue reads.
        issue_stage(it + 2, (it + 2) % NST);
    }

    // ---- drain: epilogue for the last quad ----
    if (niters > 0) {
        __syncthreads();   // make warps 0-3's s_c write visible
        const int it  = niters - 1;
        const int cur = it & 1;
        const float* pb = xs + ((it % NST) * 4) * DD;
        const int    qp = bid + it * stride;
        const float  c0 = s_c[cur][0], c1 = s_c[cur][1];
        const float  c2 = s_c[cur][2], c3 = s_c[cur][3];
        float4 xp, o;
        xp = *reinterpret_cast<const float4*>(pb + 0 * DD + tid * 4);
        o.x = fmaf(xp.x, c0, dl.x); o.y = fmaf(xp.y, c0, dl.y);
        o.z = fmaf(xp.z, c0, dl.z); o.w = fmaf(xp.w, c0, dl.w);
        __stcs(&o4[(size_t)(4 * qp + 0) * (DD / 4) + tid], o);
        xp = *reinterpret_cast<const float4*>(pb + 1 * DD + tid * 4);
        o.x = fmaf(xp.x, c1, dl.x); o.y = fmaf(xp.y, c1, dl.y);
        o.z = fmaf(xp.z, c1, dl.z); o.w = fmaf(xp.w, c1, dl.w);
        __stcs(&o4[(size_t)(4 * qp + 1) * (DD / 4) + tid], o);
        xp = *reinterpret_cast<const float4*>(pb + 2 * DD + tid * 4);
        o.x = fmaf(xp.x, c2, dl.x); o.y = fmaf(xp.y, c2, dl.y);
        o.z = fmaf(xp.z, c2, dl.z); o.w = fmaf(xp.w, c2, dl.w);
        __stcs(&o4[(size_t)(4 * qp + 2) * (DD / 4) + tid], o);
        xp = *reinterpret_cast<const float4*>(pb + 3 * DD + tid * 4);
        o.x = fmaf(xp.x, c3, dl.x); o.y = fmaf(xp.y, c3, dl.y);
        o.z = fmaf(xp.z, c3, dl.z); o.w = fmaf(xp.w, c3, dl.w);
        __stcs(&o4[(size_t)(4 * qp + 3) * (DD / 4) + tid], o);
    }
}

extern "C" void kernel_launch(void* const* d_in, const int* in_sizes, int n_in,
                              void* d_out, int out_size)
{
    const float* x0 = (const float*)d_in[0];   // inputs [B, D] f32
    const float* w  = (const float*)d_in[1];   // w [L, D, 1]  f32
    const float* b  = (const float*)d_in[2];   // b [L, D]     f32
    float* out      = (float*)d_out;           // [B, D]       f32

    const int B = in_sizes[0] / DD;
    const int smem_bytes = NST * 4 * DD * (int)sizeof(float);   // 196608

    static int sm_count = 0;
    if (sm_count == 0) {
        cudaDeviceGetAttribute(&sm_count, cudaDevAttrMultiProcessorCount, 0);
        if (sm_count <= 0) sm_count = 148;
        cudaFuncSetAttribute(crossnet_dcn_kernel,
                             cudaFuncAttributeMaxDynamicSharedMemorySize,
                             smem_bytes);
    }

    crossnet_dcn_kernel<<<sm_count, BLOCK, smem_bytes>>>(x0, w, b, out, B);
}